// round 14
// baseline (speedup 1.0000x reference)
#include <cuda_runtime.h>
#include <cuda_bf16.h>
#include <cstddef>

// WKV2D: B=8, H=16, W=16, C=256.
// k_adj = sum_taps relu(k - w[c]*manhattan_d) (+u bonus at center); out = exp(k_adj)*v.
// Sparsity: a tap at distance d is nonzero iff k > w*d. So:
//   4-tap (r=1) diamond is exact unless some k > 2*w_c  (flag bit 1)
//   12-tap (r=2) diamond is exact unless some k > 3*w_c (flag bit 2)
// Block-wide union of the predicates comes free via __syncthreads_or.
// Halo trick: -1e30 padding => relu gives exact 0, no bounds checks in fast path.
// Own-row taps come straight from registers (kr), not shared memory.
//
// Block = 8 consecutive channels x whole 16x16 image of one batch; 256 threads.
// Thread (c = t&7, s = t>>3) owns 8 horizontally-consecutive pixels of one
// channel -> every global access is a fully-utilized 32B sector.

#define B_DIM   8
#define C_DIM   256
#define CCH     8
#define PAD     2            // fast path covers r <= 2
#define TW      20           // padded row stride (16 + 2*PAD)
#define CPLANE  405          // 400 used; 405 % 32 == 21 -> near-conflict-free

__device__ __forceinline__ float relu_(float x) { return fmaxf(x, 0.0f); }

// 8 consecutive pixels of one channel, compile-time radius.
// Center tap (0,0) EXCLUDED (handled by the u-bonus init).
// di=0 row comes from the caller's registers (kr) + 2R edge LDS.
template<int R>
__device__ __forceinline__ void diamond8(const float* __restrict__ ksb, int pos0,
                                         const float kr[8], float wneg, float acc[8])
{
    float wd[2 * R + 1];
    #pragma unroll
    for (int d = 0; d <= 2 * R; ++d) wd[d] = wneg * (float)d;

    // ---- own row: registers + 2R edge cells from smem ----
    float ext[8 + 2 * R];
    #pragma unroll
    for (int j = 0; j < 2 * R; ++j) {
        const int jj = (j < R) ? j : 8 + j;          // left R, right R
        ext[jj] = ksb[pos0 - R + jj];
    }
    #pragma unroll
    for (int i = 0; i < 8; ++i) ext[R + i] = kr[i];

    #pragma unroll
    for (int i = 0; i < 8; ++i) {
        #pragma unroll
        for (int dj = -R; dj <= R; ++dj) {
            if (dj == 0) continue;                   // center handled in init
            const int adj = dj < 0 ? -dj : dj;
            acc[i] += relu_(ext[i + dj + R] + wd[adj]);
        }
    }

    // ---- other rows from smem, one segment per row serves all 8 pixels ----
    #pragma unroll
    for (int di = -R; di <= R; ++di) {
        if (di == 0) continue;
        const int adi = di < 0 ? -di : di;
        const int rr  = R - adi;
        float seg[8 + 2 * R];
        const int sbase = pos0 + di * TW - rr;
        #pragma unroll
        for (int j = 0; j < 8 + 2 * rr; ++j) seg[j] = ksb[sbase + j];
        #pragma unroll
        for (int i = 0; i < 8; ++i) {
            #pragma unroll
            for (int dj = -rr; dj <= rr; ++dj) {
                const int adj = dj < 0 ? -dj : dj;
                acc[i] += relu_(seg[i + dj + rr] + wd[adi + adj]);
            }
        }
    }
}

__global__ __launch_bounds__(256)
void wkv2d_kernel(const float* __restrict__ w,
                  const float* __restrict__ u,
                  const float* __restrict__ k,
                  const float* __restrict__ v,
                  float* __restrict__ out)
{
    __shared__ float ks[CCH * CPLANE];   // 8 padded channel planes (~13KB)

    const int b  = blockIdx.x >> 5;      // 32 channel-chunks per batch
    const int c0 = (blockIdx.x & 31) * CCH;
    const int t  = threadIdx.x;
    const int c  = t & 7;
    const int s  = t >> 3;               // 0..31
    const int y  = s >> 1;
    const int x0 = (s & 1) << 3;

    const size_t base = ((size_t)b * 256) * C_DIM + c0;
    const float* kg = k + base + c;
    const float* vg = v + base + c;
    const int px0 = (y << 4) + x0;

    // ---- issue all 16 global loads up front (deep MLP) ----
    float kr[8], vr[8];
    #pragma unroll
    for (int i = 0; i < 8; ++i) kr[i] = kg[(size_t)(px0 + i) * C_DIM];
    #pragma unroll
    for (int i = 0; i < 8; ++i) vr[i] = vg[(size_t)(px0 + i) * C_DIM];

    const float wv = w[c0 + c];
    const float uv = u[c0 + c];

    // ---- halo-only fill: 144 halo cells/plane (scalar, alignment-safe) ----
    // rows 0,1,18,19 full (4*20=80); rows 2..17 cols {0,1,18,19} (16*4=64)
    if (t < 144) {
        int row, col;
        if (t < 80) {
            int r4 = t / 20;
            col = t - r4 * 20;
            row = r4 < 2 ? r4 : r4 + 16;
        } else {
            int q = t - 80;
            int qr = q >> 2;
            int ci = q & 3;
            row = 2 + qr;
            col = ci < 2 ? ci : ci + 16;
        }
        const int pos = row * TW + col;
        #pragma unroll
        for (int p = 0; p < CCH; ++p)
            ks[p * CPLANE + pos] = -1e30f;
    }

    // ---- interior stores + radius predicates via running max ----
    float* ksb = ks + c * CPLANE;
    const int pos0 = (y + PAD) * TW + (x0 + PAD);
    float mloc = kr[0];
    #pragma unroll
    for (int i = 0; i < 8; ++i) {
        ksb[pos0 + i] = kr[i];
        if (i) mloc = fmaxf(mloc, kr[i]);
    }
    int flag = (mloc > 2.0f * wv) ? 1 : 0;       // some tap at d=2 nonzero
    flag    |= (mloc > 3.0f * wv) ? 2 : 0;       // some tap at d>=3 nonzero

    // single barrier + block-wide OR of the predicates (bar.red.or)
    const int f = __syncthreads_or(flag);

    const float wneg = -wv;

    // ---- init acc with the center term: relu(k + u) ----
    float acc[8];
    #pragma unroll
    for (int i = 0; i < 8; ++i)
        acc[i] = relu_(kr[i] + uv);

    if (!(f & 1)) {
        diamond8<1>(ksb, pos0, kr, wneg, acc);   // 4 taps: exact, d>=2 all zero
    } else if (!(f & 2)) {
        diamond8<2>(ksb, pos0, kr, wneg, acc);   // 12 taps: exact, d>=3 all zero
    } else {
        // dense exact fallback (never taken in practice): full image,
        // taps beyond the true radius add exact zeros.
        #pragma unroll
        for (int i = 0; i < 8; ++i) {
            const int xx = x0 + i;
            float a = acc[i];
            for (int iy = 0; iy < 16; ++iy) {
                const int adi = iy > y ? iy - y : y - iy;
                for (int ix = 0; ix < 16; ++ix) {
                    if (iy == y && ix == xx) continue;
                    const int adj_ = ix > xx ? ix - xx : xx - ix;
                    a += relu_(fmaf(wneg, (float)(adi + adj_),
                                    ksb[(iy + PAD) * TW + ix + PAD]));
                }
            }
            acc[i] = a;
        }
    }

    // ---- epilogue: fully-sectored stores ----
    float* og = out + base + c;
    #pragma unroll
    for (int i = 0; i < 8; ++i)
        og[(size_t)(px0 + i) * C_DIM] = __expf(acc[i]) * vr[i];
}

extern "C" void kernel_launch(void* const* d_in, const int* in_sizes, int n_in,
                              void* d_out, int out_size)
{
    const float *w = nullptr, *u = nullptr, *k = nullptr, *v = nullptr;
    for (int i = 0; i < n_in; i++) {
        if (in_sizes[i] == C_DIM) {
            if (!w) w = (const float*)d_in[i];
            else if (!u) u = (const float*)d_in[i];
        } else if (in_sizes[i] == B_DIM * 256 * C_DIM) {
            if (!k) k = (const float*)d_in[i];
            else if (!v) v = (const float*)d_in[i];
        }
    }
    wkv2d_kernel<<<B_DIM * (C_DIM / CCH), 256>>>(w, u, k, v, (float*)d_out);
}

// round 15
// speedup vs baseline: 1.3575x; 1.3575x over previous
#include <cuda_runtime.h>
#include <cuda_bf16.h>
#include <cstddef>

// WKV2D: B=8, H=16, W=16, C=256.
// k_adj = sum_taps relu(k - w[c]*manhattan_d) (+u bonus at center); out = exp(k_adj)*v.
// Sparsity: a tap at distance d is nonzero iff k > w*d:
//   4-tap (r=1) diamond exact unless some k > 2*w_c; 12-tap (r=2) unless k > 3*w_c.
// Halo trick: -1e30 padding => relu gives exact 0, no bounds checks in fast path.
//
// Block = 16 consecutive channels (two 8-channel chunks A,B) x whole 16x16 image
// of one batch; 256 threads; grid 128 (~1 block/SM, one wave).
// All 32 global loads issue at kernel entry (deep MLP); ONE barrier covers both
// tiles + both chunks' radius predicates via a 4-bit __syncthreads_or.
// Thread (c = t&7, s = t>>3) owns 8 horizontally-consecutive pixels ->
// every global access is a fully-utilized 32B sector.

#define B_DIM   8
#define C_DIM   256
#define CCH     8
#define PAD     2            // fast path covers r <= 2
#define TW      20           // padded row stride (16 + 2*PAD)
#define CPLANE  405          // 400 used; 405 % 32 == 21 -> near-conflict-free

__device__ __forceinline__ float relu_(float x) { return fmaxf(x, 0.0f); }

// 8 consecutive pixels of one channel, compile-time radius.
// Center tap (0,0) EXCLUDED (handled by the u-bonus init).
// di=0 row comes from the caller's registers (kr) + 2R edge LDS.
template<int R>
__device__ __forceinline__ void diamond8(const float* __restrict__ ksb, int pos0,
                                         const float kr[8], float wneg, float acc[8])
{
    float wd[2 * R + 1];
    #pragma unroll
    for (int d = 0; d <= 2 * R; ++d) wd[d] = wneg * (float)d;

    // ---- own row: registers + 2R edge cells from smem ----
    float ext[8 + 2 * R];
    #pragma unroll
    for (int j = 0; j < 2 * R; ++j) {
        const int jj = (j < R) ? j : 8 + j;          // left R, right R
        ext[jj] = ksb[pos0 - R + jj];
    }
    #pragma unroll
    for (int i = 0; i < 8; ++i) ext[R + i] = kr[i];

    #pragma unroll
    for (int i = 0; i < 8; ++i) {
        #pragma unroll
        for (int dj = -R; dj <= R; ++dj) {
            if (dj == 0) continue;                   // center handled in init
            const int adj = dj < 0 ? -dj : dj;
            acc[i] += relu_(ext[i + dj + R] + wd[adj]);
        }
    }

    // ---- other rows from smem, one segment per row serves all 8 pixels ----
    #pragma unroll
    for (int di = -R; di <= R; ++di) {
        if (di == 0) continue;
        const int adi = di < 0 ? -di : di;
        const int rr  = R - adi;
        float seg[8 + 2 * R];
        const int sbase = pos0 + di * TW - rr;
        #pragma unroll
        for (int j = 0; j < 8 + 2 * rr; ++j) seg[j] = ksb[sbase + j];
        #pragma unroll
        for (int i = 0; i < 8; ++i) {
            #pragma unroll
            for (int dj = -rr; dj <= rr; ++dj) {
                const int adj = dj < 0 ? -dj : dj;
                acc[i] += relu_(seg[i + dj + rr] + wd[adi + adj]);
            }
        }
    }
}

// Process one chunk after the barrier: diamond dispatch + epilogue stores.
__device__ __forceinline__ void process_chunk(const float* __restrict__ ksb, int pos0,
                                              const float kr[8], const float vr[8],
                                              float wv, float uv, int f2,
                                              int y, int x0,
                                              float* __restrict__ og)
{
    const float wneg = -wv;
    float acc[8];
    #pragma unroll
    for (int i = 0; i < 8; ++i)
        acc[i] = relu_(kr[i] + uv);                  // center term with u-bonus

    if (!(f2 & 1)) {
        diamond8<1>(ksb, pos0, kr, wneg, acc);       // exact: d>=2 taps all zero
    } else if (!(f2 & 2)) {
        diamond8<2>(ksb, pos0, kr, wneg, acc);       // exact: d>=3 taps all zero
    } else {
        // dense exact fallback (never taken in practice)
        #pragma unroll
        for (int i = 0; i < 8; ++i) {
            const int xx = x0 + i;
            float a = acc[i];
            for (int iy = 0; iy < 16; ++iy) {
                const int adi = iy > y ? iy - y : y - iy;
                for (int ix = 0; ix < 16; ++ix) {
                    if (iy == y && ix == xx) continue;
                    const int adj_ = ix > xx ? ix - xx : xx - ix;
                    a += relu_(fmaf(wneg, (float)(adi + adj_),
                                    ksb[(iy + PAD) * TW + ix + PAD]));
                }
            }
            acc[i] = a;
        }
    }

    #pragma unroll
    for (int i = 0; i < 8; ++i)
        og[(size_t)i * C_DIM] = __expf(acc[i]) * vr[i];
}

__global__ __launch_bounds__(256)
void wkv2d_kernel(const float* __restrict__ w,
                  const float* __restrict__ u,
                  const float* __restrict__ k,
                  const float* __restrict__ v,
                  float* __restrict__ out)
{
    __shared__ float ks[2 * CCH * CPLANE];   // 16 padded channel planes (~26KB)

    const int b  = blockIdx.x >> 4;          // 16 chunk-pairs per batch
    const int c0 = (blockIdx.x & 15) * (2 * CCH);
    const int t  = threadIdx.x;
    const int c  = t & 7;
    const int s  = t >> 3;                   // 0..31
    const int y  = s >> 1;
    const int x0 = (s & 1) << 3;

    const size_t baseA = ((size_t)b * 256) * C_DIM + c0;      // chunk A channels
    const size_t baseB = baseA + CCH;                          // chunk B channels
    const int px0 = (y << 4) + x0;
    const size_t off0 = (size_t)px0 * C_DIM + c;

    // ---- issue all 32 global loads up front (deep MLP, one latency head) ----
    float krA[8], krB[8], vrA[8], vrB[8];
    #pragma unroll
    for (int i = 0; i < 8; ++i) krA[i] = k[baseA + off0 + (size_t)i * C_DIM];
    #pragma unroll
    for (int i = 0; i < 8; ++i) krB[i] = k[baseB + off0 + (size_t)i * C_DIM];
    #pragma unroll
    for (int i = 0; i < 8; ++i) vrA[i] = v[baseA + off0 + (size_t)i * C_DIM];
    #pragma unroll
    for (int i = 0; i < 8; ++i) vrB[i] = v[baseB + off0 + (size_t)i * C_DIM];

    const float wvA = w[c0 + c],       uvA = u[c0 + c];
    const float wvB = w[c0 + CCH + c], uvB = u[c0 + CCH + c];

    // ---- halo-only fill: 144 halo cells/plane, 16 planes ----
    if (t < 144) {
        int row, col;
        if (t < 80) {
            int r4 = t / 20;
            col = t - r4 * 20;
            row = r4 < 2 ? r4 : r4 + 16;
        } else {
            int q = t - 80;
            int qr = q >> 2;
            int ci = q & 3;
            row = 2 + qr;
            col = ci < 2 ? ci : ci + 16;
        }
        const int pos = row * TW + col;
        #pragma unroll
        for (int p = 0; p < 2 * CCH; ++p)
            ks[p * CPLANE + pos] = -1e30f;
    }

    // ---- interior stores (both tiles) + radius predicates via running max ----
    float* ksbA = ks + c * CPLANE;
    float* ksbB = ks + (CCH + c) * CPLANE;
    const int pos0 = (y + PAD) * TW + (x0 + PAD);

    float mA = krA[0], mB = krB[0];
    #pragma unroll
    for (int i = 0; i < 8; ++i) {
        ksbA[pos0 + i] = krA[i];
        ksbB[pos0 + i] = krB[i];
        if (i) { mA = fmaxf(mA, krA[i]); mB = fmaxf(mB, krB[i]); }
    }
    int flag  = (mA > 2.0f * wvA) ? 1 : 0;
    flag     |= (mA > 3.0f * wvA) ? 2 : 0;
    flag     |= (mB > 2.0f * wvB) ? 4 : 0;
    flag     |= (mB > 3.0f * wvB) ? 8 : 0;

    // single barrier: both tiles + all predicates (bar.red.or)
    const int f = __syncthreads_or(flag);

    // ---- chunk A, then chunk B (B's loads already resident) ----
    process_chunk(ksbA, pos0, krA, vrA, wvA, uvA,  f       & 3, y, x0,
                  out + baseA + off0);
    process_chunk(ksbB, pos0, krB, vrB, wvB, uvB, (f >> 2) & 3, y, x0,
                  out + baseB + off0);
}

extern "C" void kernel_launch(void* const* d_in, const int* in_sizes, int n_in,
                              void* d_out, int out_size)
{
    const float *w = nullptr, *u = nullptr, *k = nullptr, *v = nullptr;
    for (int i = 0; i < n_in; i++) {
        if (in_sizes[i] == C_DIM) {
            if (!w) w = (const float*)d_in[i];
            else if (!u) u = (const float*)d_in[i];
        } else if (in_sizes[i] == B_DIM * 256 * C_DIM) {
            if (!k) k = (const float*)d_in[i];
            else if (!v) v = (const float*)d_in[i];
        }
    }
    wkv2d_kernel<<<B_DIM * 16, 256>>>(w, u, k, v, (float*)d_out);
}